// round 17
// baseline (speedup 1.0000x reference)
#include <cuda_runtime.h>
#include <cuda_fp16.h>
#include <math.h>
#include <stdint.h>

#define DIM    512
#define SEQ    4096
#define BATCH  8
#define ROWS   (BATCH*SEQ)      // 32768
#define DFF    (4*DIM)          // 2048
#define HEADS  8
#define HD     64
#define NBH    (BATCH*HEADS)    // 64
#define NSPL   16
#define EPSLN  1e-5f

// ---------------- scratch (device globals) ---------------------------------
__device__ __half g_seasonal[ROWS*DIM];   // fp16: direct-output rounding ~1.6e-4 RMS
__device__ __half g_trend   [ROWS*DIM];
__device__ __half g_ln_hi[ROWS*DIM];
__device__ __half g_ln_lo[ROWS*DIM];
__device__ __half g_q[ROWS*DIM];     // q single fp16, 1-pass (q-path tolerant)
__device__ __half g_khi[ROWS*DIM];   // k,v fp16 hi/lo pairs (exact to ~2^-22)
__device__ __half g_klo[ROWS*DIM];
__device__ __half g_vhi[ROWS*DIM];
__device__ __half g_vlo[ROWS*DIM];
__device__ float  g_kvp[NSPL*NBH*HD*HD];
__device__ __half g_mt[BATCH*DIM*DIM];
__device__ __half g_hid[(size_t)ROWS*DFF];
__device__ __half g_wqkv[3*DIM*DIM];
__device__ __half g_wf1[DIM*DFF];
__device__ __half g_wf2[DFF*DIM];

// ---------------- helpers --------------------------------------------------
__device__ __forceinline__ uint32_t smem_to_u32(const void* p) {
    uint32_t a;
    asm("{ .reg .u64 t; cvta.to.shared.u64 t, %1; cvt.u32.u64 %0, t; }" : "=r"(a) : "l"(p));
    return a;
}
#define CP16(dst, src) \
    asm volatile("cp.async.cg.shared.global [%0], [%1], 16;" :: "r"(dst), "l"(src))
#define CP_COMMIT() asm volatile("cp.async.commit_group;" ::: "memory")
__device__ __forceinline__ void ldsm_x4(uint32_t (&r)[4], uint32_t addr) {
    asm volatile("ldmatrix.sync.aligned.m8n8.x4.shared.b16 {%0,%1,%2,%3}, [%4];"
        : "=r"(r[0]), "=r"(r[1]), "=r"(r[2]), "=r"(r[3]) : "r"(addr));
}
__device__ __forceinline__ void ldsm_x4_t(uint32_t (&r)[4], uint32_t addr) {
    asm volatile("ldmatrix.sync.aligned.m8n8.x4.trans.shared.b16 {%0,%1,%2,%3}, [%4];"
        : "=r"(r[0]), "=r"(r[1]), "=r"(r[2]), "=r"(r[3]) : "r"(addr));
}
__device__ __forceinline__ void mma16816(float* c, const uint32_t* a, uint32_t b0, uint32_t b1) {
    asm volatile("mma.sync.aligned.m16n8k16.row.col.f32.f16.f16.f32 "
        "{%0,%1,%2,%3}, {%4,%5,%6,%7}, {%8,%9}, {%0,%1,%2,%3};"
        : "+f"(c[0]), "+f"(c[1]), "+f"(c[2]), "+f"(c[3])
        : "r"(a[0]), "r"(a[1]), "r"(a[2]), "r"(a[3]), "r"(b0), "r"(b1));
}
#define SW64(off) ((off) ^ (((off) >> 3) & 0x30))

__device__ __forceinline__ void split_store2(__half* hi, __half* lo,
                                             size_t idx, float a, float b) {
    __half ha = __float2half(a), hb = __float2half(b);
    __half2 h; h.x = ha; h.y = hb;
    *(__half2*)(hi + idx) = h;
    __half2 l;
    l.x = __float2half(a - __half2float(ha));
    l.y = __float2half(b - __half2float(hb));
    *(__half2*)(lo + idx) = l;
}
__device__ __forceinline__ void split_store4(__half* hi, __half* lo,
                                             long idx, float4 o) {
    split_store2(hi, lo, idx,     o.x, o.y);
    split_store2(hi, lo, idx + 2, o.z, o.w);
}

// ---------------- all weight prep in ONE launch ----------------------------
__device__ __forceinline__ void wsplit_tile(const float* __restrict__ W,
                                            __half* __restrict__ T,
                                            int K, int N, int bx, int by,
                                            float (*t)[33]) {
    int tx = threadIdx.x & 31, ty = threadIdx.x >> 5;
    int x = bx*32 + tx;
    for (int i = ty; i < 32; i += 8)
        t[i][tx] = W[(long)(by*32 + i)*N + x];
    __syncthreads();
    int kk = by*32 + tx;
    for (int i = ty; i < 32; i += 8) {
        int n = bx*32 + i;
        T[(long)n*K + kk] = __float2half(t[tx][i]);
    }
}

__global__ __launch_bounds__(256)
void wsplit_all_kernel(const float* __restrict__ Wq, const float* __restrict__ Wk,
                       const float* __restrict__ Wv, const float* __restrict__ Wf1,
                       const float* __restrict__ Wf2,
                       __half* __restrict__ qkv, __half* __restrict__ f1,
                       __half* __restrict__ f2) {
    __shared__ float t[32][33];
    int id = blockIdx.x;
    if (id < 768) {
        int bx = id % 48, by = id / 48;
        int mid = bx >> 4;
        const float* W = (mid == 0) ? Wq : (mid == 1) ? Wk : Wv;
        wsplit_tile(W, qkv + (size_t)mid*DIM*DIM, DIM, DIM, bx & 15, by, t);
    } else if (id < 768 + 1024) {
        int r = id - 768;
        wsplit_tile(Wf1, f1, DIM, DFF, r % 64, r / 64, t);
    } else {
        int r = id - 1792;
        wsplit_tile(Wf2, f2, DFF, DIM, r % 16, r / 16, t);
    }
}

// ---------------- block reduce ---------------------------------------------
__device__ __forceinline__ void block_reduce2_128(float& a, float& b) {
    #pragma unroll
    for (int o = 16; o > 0; o >>= 1) {
        a += __shfl_down_sync(0xffffffffu, a, o);
        b += __shfl_down_sync(0xffffffffu, b, o);
    }
    __shared__ float sa[4], sb[4];
    int w = threadIdx.x >> 5, l = threadIdx.x & 31;
    if (l == 0) { sa[w] = a; sb[w] = b; }
    __syncthreads();
    a = sa[0]+sa[1]+sa[2]+sa[3];
    b = sb[0]+sb[1]+sb[2]+sb[3];
}

// ---------------- decomposition + LN1 --------------------------------------
__global__ __launch_bounds__(128)
void decomp_ln_kernel(const float* __restrict__ x,
                      const float* __restrict__ g, const float* __restrict__ b,
                      __half* __restrict__ trend,
                      __half* __restrict__ lnhi, __half* __restrict__ lnlo)
{
    long row = blockIdx.x;
    int n = (int)(row % SEQ), tid = threadIdx.x;
    const float* xr = x + row*DIM;
    float4 x0 = *(const float4*)(xr + tid*4);
    float4 xm = make_float4(0,0,0,0), xp = make_float4(0,0,0,0);
    if (n != 0)     xm = *(const float4*)(xr - DIM + tid*4);
    if (n != SEQ-1) xp = *(const float4*)(xr + DIM + tid*4);
    const float inv3 = 1.f/3.f;
    float4 t, s;
    t.x=(xm.x+x0.x+xp.x)*inv3; s.x=x0.x-t.x;
    t.y=(xm.y+x0.y+xp.y)*inv3; s.y=x0.y-t.y;
    t.z=(xm.z+x0.z+xp.z)*inv3; s.z=x0.z-t.z;
    t.w=(xm.w+x0.w+xp.w)*inv3; s.w=x0.w-t.w;
    __half2 t0; t0.x = __float2half(t.x); t0.y = __float2half(t.y);
    __half2 t1; t1.x = __float2half(t.z); t1.y = __float2half(t.w);
    *(__half2*)(trend + row*DIM + tid*4)     = t0;
    *(__half2*)(trend + row*DIM + tid*4 + 2) = t1;
    float sum = s.x+s.y+s.z+s.w, sq = s.x*s.x+s.y*s.y+s.z*s.z+s.w*s.w;
    block_reduce2_128(sum, sq);
    float mean = sum*(1.f/DIM), var = sq*(1.f/DIM)-mean*mean;
    float rs = rsqrtf(var + EPSLN);
    float4 gv = *(const float4*)(g + tid*4);
    float4 bv = *(const float4*)(b + tid*4);
    float4 o;
    o.x=(s.x-mean)*rs*gv.x+bv.x; o.y=(s.y-mean)*rs*gv.y+bv.y;
    o.z=(s.z-mean)*rs*gv.z+bv.z; o.w=(s.w-mean)*rs*gv.w+bv.w;
    split_store4(lnhi, lnlo, row*DIM + tid*4, o);
}

// ---------------- LN2 (fp16 in, hi only out) -------------------------------
__global__ __launch_bounds__(128)
void ln_kernel(const __half* __restrict__ in,
               const float* __restrict__ g, const float* __restrict__ b,
               __half* __restrict__ lnhi)
{
    long row = blockIdx.x;
    int tid = threadIdx.x;
    __half2 i0 = *(const __half2*)(in + row*DIM + tid*4);
    __half2 i1 = *(const __half2*)(in + row*DIM + tid*4 + 2);
    float2 f0 = __half22float2(i0);
    float2 f1 = __half22float2(i1);
    float4 s = make_float4(f0.x, f0.y, f1.x, f1.y);
    float sum = s.x+s.y+s.z+s.w, sq = s.x*s.x+s.y*s.y+s.z*s.z+s.w*s.w;
    block_reduce2_128(sum, sq);
    float mean = sum*(1.f/DIM), var = sq*(1.f/DIM)-mean*mean;
    float rs = rsqrtf(var + EPSLN);
    float4 gv = *(const float4*)(g + tid*4);
    float4 bv = *(const float4*)(b + tid*4);
    __half2 p0, p1;
    p0.x = __float2half((s.x-mean)*rs*gv.x+bv.x);
    p0.y = __float2half((s.y-mean)*rs*gv.y+bv.y);
    p1.x = __float2half((s.z-mean)*rs*gv.z+bv.z);
    p1.y = __float2half((s.w-mean)*rs*gv.w+bv.w);
    *(__half2*)(lnhi + row*DIM + tid*4)     = p0;
    *(__half2*)(lnhi + row*DIM + tid*4 + 2) = p1;
}

// ---------------- fp16 mma GEMM: block 128x128, warp 32x64, 2 CTA/SM -------
// NPASS=2: Ahi*B + Alo*B ; NPASS=1: Ahi*B
// EPI=5 (QKV): q tiles (bx<4) run 1-pass; k/v tiles (bx>=4) run 2-pass.
// PB=1: B per-batch (Mt)
// EPI: 3 GELU->Chi, 4 out = acc + bias + res1h(seasonal) + res2h(trend) -> Cf,
//      5 fused QKV, 6 seasonal(fp16) = acc + bias + res1(x) - res2h(trend) -> Chi
template<int EPI, int NPASS, int PB>
__global__ __launch_bounds__(256, 2)
void mma_gemm(const __half* __restrict__ Ahi, const __half* __restrict__ Alo,
              const __half* __restrict__ B,
              const float* __restrict__ bias, const float* __restrict__ bias2,
              const float* __restrict__ bias3,
              const float* __restrict__ res1, const __half* __restrict__ res1h,
              const __half* __restrict__ res2h,
              float* __restrict__ Cf,
              __half* __restrict__ Khi, __half* __restrict__ Klo,
              __half* __restrict__ Vhi, __half* __restrict__ Vlo,
              __half* __restrict__ Chi,
              int K, int NB)
{
    constexpr int STAGEB = (NPASS == 2) ? 24576 : 16384;
    constexpr int OFF_AL = 8192;
    constexpr int OFF_B  = (NPASS == 2) ? 16384 : 8192;

    extern __shared__ char smem[];
    const uint32_t sb = smem_to_u32(smem);
    const int tid = threadIdx.x, wid = tid >> 5, lane = tid & 31;
    const int bx = blockIdx.x, by = blockIdx.y;
    const int wm = wid & 3;
    const int wn = wid >> 2;

    // q tiles skip the lo pass (q-path tolerant; k/v stay full 2-pass)
    const bool pass2 = (NPASS == 2) && (EPI != 5 || bx >= 4);

    const size_t K2 = (size_t)K * 2;
    const char* gAh = (const char*)Ahi + (size_t)(by*128)*K2;
    const char* gAl = (NPASS == 2) ? (const char*)Alo + (size_t)(by*128)*K2 : nullptr;
    size_t boff = PB ? (size_t)(by >> 5) * DIM * DIM * 2 : 0;
    const char* gB = (const char*)B + boff + (size_t)(bx*128)*K2;

    const int lr = tid >> 2, lc = (tid & 3) * 16;

    auto LOAD = [&](int ck, int buf) {
        uint32_t s0 = sb + buf*STAGEB;
        size_t kofs = (size_t)ck * 64;
        #pragma unroll
        for (int j = 0; j < 2; j++) {
            int r = lr + j*64;
            uint32_t so = SW64(r*64 + lc);
            size_t go = (size_t)r*K2 + kofs + lc;
            CP16(s0 + so, gAh + go);
            if (NPASS == 2) { if (pass2) CP16(s0 + OFF_AL + so, gAl + go); }
            CP16(s0 + OFF_B + so, gB + go);
        }
    };

    float acc[2][8][4];
    #pragma unroll
    for (int i = 0; i < 2; i++)
        #pragma unroll
        for (int j = 0; j < 8; j++)
            #pragma unroll
            for (int r = 0; r < 4; r++) acc[i][j][r] = 0.f;

    const int aRow = wm*32 + (lane & 15);
    const int aK   = (lane >> 4) * 8;
    const int bN   = wn*64 + (lane & 7) + ((lane >> 4) & 1) * 8;
    const int bK   = ((lane >> 3) & 1) * 8;

    const int nck = K >> 5;
    LOAD(0, 0); CP_COMMIT();
    LOAD(1, 1); CP_COMMIT();
    LOAD(2, 2); CP_COMMIT();

    for (int ck = 0; ck < nck; ck++) {
        int rem = nck - 1 - ck;
        if (rem >= 2)      asm volatile("cp.async.wait_group 2;" ::: "memory");
        else if (rem == 1) asm volatile("cp.async.wait_group 1;" ::: "memory");
        else               asm volatile("cp.async.wait_group 0;" ::: "memory");
        __syncthreads();
        if (ck + 3 < nck) { LOAD(ck + 3, (ck + 3) & 3); CP_COMMIT(); }

        uint32_t s0 = sb + (ck & 3) * STAGEB;
        #pragma unroll
        for (int kk = 0; kk < 32; kk += 16) {
            uint32_t ah[2][4], bb[4][4];
            #pragma unroll
            for (int mt = 0; mt < 2; mt++)
                ldsm_x4(ah[mt], s0 + SW64((aRow + mt*16)*64 + (kk + aK)*2));
            #pragma unroll
            for (int nt4 = 0; nt4 < 4; nt4++)
                ldsm_x4(bb[nt4], s0 + OFF_B + SW64((bN + nt4*16)*64 + (kk + bK)*2));
            #pragma unroll
            for (int mt = 0; mt < 2; mt++)
                #pragma unroll
                for (int nt = 0; nt < 8; nt++)
                    mma16816(acc[mt][nt], ah[mt], bb[nt>>1][(nt&1)*2], bb[nt>>1][(nt&1)*2+1]);
            if (NPASS == 2) {
                if (pass2) {
                    uint32_t al[2][4];
                    #pragma unroll
                    for (int mt = 0; mt < 2; mt++)
                        ldsm_x4(al[mt], s0 + OFF_AL + SW64((aRow + mt*16)*64 + (kk + aK)*2));
                    #pragma unroll
                    for (int mt = 0; mt < 2; mt++)
                        #pragma unroll
                        for (int nt = 0; nt < 8; nt++)
                            mma16816(acc[mt][nt], al[mt], bb[nt>>1][(nt&1)*2], bb[nt>>1][(nt&1)*2+1]);
                }
            }
        }
    }
    // epilogue
    const size_t Nl = (EPI == 5) ? (size_t)DIM : (size_t)NB;
    #pragma unroll
    for (int mt = 0; mt < 2; mt++) {
        #pragma unroll
        for (int nt = 0; nt < 8; nt++) {
            const float* c = acc[mt][nt];
            long row0 = (long)by*128 + wm*32 + mt*16 + (lane >> 2);
            if (EPI == 5) {
                int mid = bx >> 2;
                int cl = (bx & 3)*128 + wn*64 + nt*8 + (lane & 3)*2;
                const float* bp = (mid == 0) ? bias : (mid == 1) ? bias2 : bias3;
                float2 bb2 = *(const float2*)&bp[cl];
                float v[4] = { c[0]+bb2.x, c[1]+bb2.y, c[2]+bb2.x, c[3]+bb2.y };
                if (mid < 2) {
                    #pragma unroll
                    for (int r = 0; r < 4; r++) v[r] = (v[r] > 0.f) ? (v[r]+1.f) : expf(v[r]);
                }
                if (mid == 0) {
                    __half2 p0; p0.x = __float2half(v[0]); p0.y = __float2half(v[1]);
                    __half2 p1; p1.x = __float2half(v[2]); p1.y = __float2half(v[3]);
                    *(__half2*)(Chi + row0*Nl + cl)     = p0;
                    *(__half2*)(Chi + (row0+8)*Nl + cl) = p1;
                } else {
                    __half* Hp = (mid == 1) ? Khi : Vhi;
                    __half* Lp = (mid == 1) ? Klo : Vlo;
                    split_store2(Hp, Lp, row0*Nl + cl,     v[0], v[1]);
                    split_store2(Hp, Lp, (row0+8)*Nl + cl, v[2], v[3]);
                }
            } else {
                int col = bx*128 + wn*64 + nt*8 + (lane & 3)*2;
                float2 bb2 = *(const float2*)&bias[col];
                float v[4] = { c[0]+bb2.x, c[1]+bb2.y, c[2]+bb2.x, c[3]+bb2.y };
                if (EPI == 3) {
                    #pragma unroll
                    for (int r = 0; r < 4; r++)
                        v[r] = 0.5f*v[r]*(1.f + erff(v[r]*0.70710678118654752f));
                } else if (EPI == 4) {
                    float2 sa = __half22float2(*(const __half2*)(res1h + row0*Nl + col));
                    float2 sb2 = __half22float2(*(const __half2*)(res1h + (row0+8)*Nl + col));
                    float2 tf0 = __half22float2(*(const __half2*)(res2h + row0*Nl + col));
                    float2 tf1 = __half22float2(*(const __half2*)(res2h + (row0+8)*Nl + col));
                    v[0] += sa.x + tf0.x; v[1] += sa.y + tf0.y;
                    v[2] += sb2.x + tf1.x; v[3] += sb2.y + tf1.y;
                } else if (EPI == 6) {
                    float2 xa = *(const float2*)&res1[row0*Nl + col];
                    float2 xb = *(const float2*)&res1[(row0+8)*Nl + col];
                    float2 ta = __half22float2(*(const __half2*)(res2h + row0*Nl + col));
                    float2 tb = __half22float2(*(const __half2*)(res2h + (row0+8)*Nl + col));
                    v[0] += xa.x - ta.x; v[1] += xa.y - ta.y;
                    v[2] += xb.x - tb.x; v[3] += xb.y - tb.y;
                }
                if (EPI == 3 || EPI == 6) {
                    __half2 p0; p0.x = __float2half(v[0]); p0.y = __float2half(v[1]);
                    __half2 p1; p1.x = __float2half(v[2]); p1.y = __float2half(v[3]);
                    *(__half2*)(Chi + row0*Nl + col)     = p0;
                    *(__half2*)(Chi + (row0+8)*Nl + col) = p1;
                } else {
                    *(float2*)&Cf[row0*Nl + col]     = make_float2(v[0], v[1]);
                    *(float2*)&Cf[(row0+8)*Nl + col] = make_float2(v[2], v[3]);
                }
            }
        }
    }
}

// ---------------- KV state via tensor cores (3-pass hi/lo, 2 CTA/SM) --------
__global__ __launch_bounds__(256, 2)
void kv_mma_kernel(const __half* __restrict__ khi, const __half* __restrict__ klo,
                   const __half* __restrict__ vhi, const __half* __restrict__ vlo,
                   float* __restrict__ kvp)
{
    int bh = blockIdx.x, split = blockIdx.y;
    int b = bh >> 3, h = bh & 7;
    __shared__ __align__(16) __half sm[2][4][32][72];
    const uint32_t sb0 = smem_to_u32(sm);
    int tid = threadIdx.x, wid = tid >> 5, lane = tid & 31;
    int wm = wid & 3, wn = wid >> 2;
    const int n0beg = split * (SEQ/NSPL);
    size_t off = ((size_t)b*SEQ*DIM + h*HD) * 2;
    const char* base0 = (const char*)khi + off;
    const char* base1 = (const char*)klo + off;
    const char* base2 = (const char*)vhi + off;
    const char* base3 = (const char*)vlo + off;

    const int lr = tid >> 3, lch = tid & 7;
    auto LOAD = [&](int it, int buf) {
        size_t g = (size_t)(n0beg + it*32 + lr) * (DIM*2) + lch*16;
        uint32_t so = sb0 + (uint32_t)(buf*4*32 + lr)*144 + lch*16;
        CP16(so,              base0 + g);
        CP16(so + 32*144,     base1 + g);
        CP16(so + 2*32*144,   base2 + g);
        CP16(so + 3*32*144,   base3 + g);
    };

    float c[4][4];
    #pragma unroll
    for (int i = 0; i < 4; i++)
        #pragma unroll
        for (int j = 0; j < 4; j++) c[i][j] = 0.f;

    const int NIT = SEQ/NSPL/32;
    LOAD(0, 0); CP_COMMIT();
    for (int it = 0; it < NIT; it++) {
        if (it + 1 < NIT) {
            LOAD(it + 1, (it + 1) & 1); CP_COMMIT();
            asm volatile("cp.async.wait_group 1;" ::: "memory");
        } else {
            asm volatile("cp.async.wait_group 0;" ::: "memory");
        }
        __syncthreads();
        int buf = it & 1;
        uint32_t sA  = sb0 + (uint32_t)(buf*4*32)*144;
        uint32_t sAl = sA + 32*144;
        uint32_t sBh = sA + 2*32*144;
        uint32_t sBl = sA + 3*32*144;
        #pragma unroll
        for (int s = 0; s < 2; s++) {
            int n0 = s*16;
            int arow = n0 + (lane & 7) + ((lane >> 4) & 1)*8;
            int acol = wm*16 + ((lane >> 3) & 1)*8;
            uint32_t aoff = (uint32_t)arow*144 + acol*2;
            uint32_t ahi[4], alo[4];
            ldsm_x4_t(ahi, sA + aoff);
            ldsm_x4_t(alo, sAl + aoff);
            int brow = n0 + (lane & 7) + ((lane >> 3) & 1)*8;
            #pragma unroll
            for (int jh = 0; jh < 2; jh++) {
                int bcol = wn*32 + jh*16 + (lane >> 4)*8;
                uint32_t boff = (uint32_t)brow*144 + bcol*2;
                uint32_t bvh[4], bvl[4];
                ldsm_x4_t(bvh, sBh + boff);
                ldsm_x4_t(bvl, sBl + boff);
                mma16816(c[jh*2],   ahi, bvh[0], bvh[1]);
                mma16816(c[jh*2+1], ahi, bvh[2], bvh[3]);
                mma16816(c[jh*2],   ahi, bvl[0], bvl[1]);
                mma16816(c[jh*2+1], ahi, bvl[2], bvl[3]);
                mma16816(c[jh*2],   alo, bvh[0], bvh[1]);
                mma16816(c[jh*2+1], alo, bvh[2], bvh[3]);
            }
        }
        __syncthreads();
    }
    float* dst = kvp + ((long)split*NBH + bh)*(HD*HD);
    int g = lane >> 2, tig = lane & 3;
    #pragma unroll
    for (int jt = 0; jt < 4; jt++) {
        int j = wn*32 + jt*8 + tig*2;
        int i = wm*16 + g;
        *(float2*)&dst[i*HD + j]       = make_float2(c[jt][0], c[jt][1]);
        *(float2*)&dst[(i+8)*HD + j]   = make_float2(c[jt][2], c[jt][3]);
    }
}

// ---------------- Mt[b] = (blockdiag kv_h) @ Wo (reduce fused in) ----------
__global__ __launch_bounds__(256)
void kvwo_kernel(const float* __restrict__ kvp, const float* __restrict__ Wo,
                 __half* __restrict__ M)
{
    int jt = blockIdx.x, h = blockIdx.y, b = blockIdx.z;
    __shared__ float skv[64][65];
    __shared__ float swo[64][64];
    int tid = threadIdx.x;
    int bh = b*HEADS + h;
    for (int i = tid; i < HD*HD; i += 256) {
        float s = 0.f;
        #pragma unroll
        for (int sp = 0; sp < NSPL; sp++)
            s += kvp[((long)sp*NBH + bh)*(HD*HD) + i];
        skv[i >> 6][i & 63] = s;
    }
    for (int i = tid; i < 64*64; i += 256) {
        int f = i >> 6, c = i & 63;
        swo[f][c] = Wo[(size_t)(h*HD + f)*DIM + jt*64 + c];
    }
    __syncthreads();
    int d = tid & 63;
    int jbase = (tid >> 6) * 16;
    float acc[16];
    #pragma unroll
    for (int j = 0; j < 16; j++) acc[j] = 0.f;
    #pragma unroll 8
    for (int f = 0; f < 64; f++) {
        float kvv = skv[d][f];
        #pragma unroll
        for (int j = 0; j < 16; j++) acc[j] += kvv * swo[f][jbase + j];
    }
    #pragma unroll
    for (int j = 0; j < 16; j++) {
        int jglob = jt*64 + jbase + j;
        M[((size_t)b*DIM + jglob)*DIM + h*HD + d] = __float2half(acc[j]);
    }
}

// ---------------- launcher -------------------------------------------------
#define SMEM2 (4*24576)
#define SMEM1 (4*16384)

extern "C" void kernel_launch(void* const* d_in, const int* in_sizes, int n_in,
                              void* d_out, int out_size)
{
    const float* x   = (const float*)d_in[0];
    const float* Wq  = (const float*)d_in[1];
    const float* bq  = (const float*)d_in[2];
    const float* Wk  = (const float*)d_in[3];
    const float* bk  = (const float*)d_in[4];
    const float* Wv  = (const float*)d_in[5];
    const float* bv  = (const float*)d_in[6];
    const float* Wo  = (const float*)d_in[7];
    const float* bo  = (const float*)d_in[8];
    const float* g1  = (const float*)d_in[9];
    const float* b1  = (const float*)d_in[10];
    const float* g2  = (const float*)d_in[11];
    const float* b2  = (const float*)d_in[12];
    const float* Wf1 = (const float*)d_in[13];
    const float* bf1 = (const float*)d_in[14];
    const float* Wf2 = (const float*)d_in[15];
    const float* bf2 = (const float*)d_in[16];
    float* out = (float*)d_out;

    float *kvp;
    __half *seasonal, *trend, *lnhi, *lnlo, *q, *khi, *klo, *vhi, *vlo, *mt, *hid;
    __half *wqkv, *wf1, *wf2;
    cudaGetSymbolAddress((void**)&seasonal, g_seasonal);
    cudaGetSymbolAddress((void**)&trend,    g_trend);
    cudaGetSymbolAddress((void**)&lnhi,     g_ln_hi);
    cudaGetSymbolAddress((void**)&lnlo,     g_ln_lo);
    cudaGetSymbolAddress((void**)&q,        g_q);
    cudaGetSymbolAddress((void**)&khi,      g_khi);
    cudaGetSymbolAddress((void**)&klo,      g_klo);
    cudaGetSymbolAddress((void**)&vhi,      g_vhi);
    cudaGetSymbolAddress((void**)&vlo,      g_vlo);
    cudaGetSymbolAddress((void**)&kvp,      g_kvp);
    cudaGetSymbolAddress((void**)&mt,       g_mt);
    cudaGetSymbolAddress((void**)&hid,      g_hid);
    cudaGetSymbolAddress((void**)&wqkv,     g_wqkv);
    cudaGetSymbolAddress((void**)&wf1,      g_wf1);
    cudaGetSymbolAddress((void**)&wf2,      g_wf2);

    cudaFuncSetAttribute(mma_gemm<5,2,0>, cudaFuncAttributeMaxDynamicSharedMemorySize, SMEM2);
    cudaFuncSetAttribute(mma_gemm<6,1,1>, cudaFuncAttributeMaxDynamicSharedMemorySize, SMEM1);
    cudaFuncSetAttribute(mma_gemm<3,1,0>, cudaFuncAttributeMaxDynamicSharedMemorySize, SMEM1);
    cudaFuncSetAttribute(mma_gemm<4,1,0>, cudaFuncAttributeMaxDynamicSharedMemorySize, SMEM1);

    // 0) all weight prep in one launch
    wsplit_all_kernel<<<2816, 256>>>(Wq, Wk, Wv, Wf1, Wf2, wqkv, wf1, wf2);

    // 1) decomposition + LN1 -> trend fp16, ln fp16 hi/lo
    decomp_ln_kernel<<<ROWS, 128>>>(x, g1, b1, trend, lnhi, lnlo);

    // 2) fused QKV (q tiles 1-pass; k,v tiles 2-pass -> fp16 hi/lo)
    mma_gemm<5,2,0><<<dim3(12, ROWS/128), 256, SMEM2>>>(lnhi, lnlo, wqkv,
        bq, bk, bv, nullptr, nullptr, nullptr, nullptr, khi, klo, vhi, vlo, q, DIM, 3*DIM);

    // 3) KV state via tensor cores (3-pass hi/lo)
    kv_mma_kernel<<<dim3(NBH, NSPL), 256>>>(khi, klo, vhi, vlo, kvp);

    // 4) Mt[b] = blockdiag(kv) @ Wo (split-reduce fused, fp16 out)
    kvwo_kernel<<<dim3(8, HEADS, BATCH), 256>>>(kvp, Wo, mt);

    // 5) seasonal(fp16) = q @ Mt[b] + bo + x - trend  (1-pass fp16)
    mma_gemm<6,1,1><<<dim3(DIM/128, ROWS/128), 256, SMEM1>>>(q, nullptr, mt,
        bo, nullptr, nullptr, x, nullptr, trend, nullptr, nullptr, nullptr, nullptr,
        nullptr, seasonal, DIM, DIM);

    // 6) LN2 (fp16 in, hi only out)
    ln_kernel<<<ROWS, 128>>>(seasonal, g2, b2, lnhi);

    // 7) FFN up + GELU -> fp16 hidden (1-pass)
    mma_gemm<3,1,0><<<dim3(DFF/128, ROWS/128), 256, SMEM1>>>(lnhi, nullptr, wf1,
        bf1, nullptr, nullptr, nullptr, nullptr, nullptr, nullptr, nullptr, nullptr,
        nullptr, nullptr, hid, DIM, DFF);

    // 8) FFN down + seasonal(fp16) + trend(fp16) -> out (1-pass)
    mma_gemm<4,1,0><<<dim3(DIM/128, ROWS/128), 256, SMEM1>>>(hid, nullptr, wf2,
        bf2, nullptr, nullptr, nullptr, seasonal, trend, out, nullptr, nullptr, nullptr,
        nullptr, nullptr, DFF, DIM);
}